// round 11
// baseline (speedup 1.0000x reference)
#include <cuda_runtime.h>
#include <cuda_fp16.h>
#include <mma.h>
#include <cstdint>

using namespace nvcuda;

// Deformable conv2d: B=2, CIN=64, H=128, W=256, COUT=64, K=3, s=1, p=1, d=1
#define B_N   2
#define C_IN  64
#define H_IN  128
#define W_IN  256
#define C_OUT 64
#define NTAP  9
#define H_O   128
#define W_O   256
#define HW    (H_IN * W_IN)     // 32768
#define HWO   (H_O * W_O)       // 32768
#define NPIX  (B_N * HWO)       // 65536

#define TPX   128               // pixels (M) per CTA tile
#define TPB   256               // 8 warps

#define ALD   72                // A smem leading dim (fp16), mult of 8
#define WLD   72                // W smem leading dim

// dynamic smem (bytes), 72 KB total -> 3 CTAs/SM:
//   A bufs : 2 * 128*72*2 = 36864   (bias tile overlaid at start of buf 0)
//   W bufs : 2 * 64*72*2  = 18432
//   Pidx   : ushort4 * 128*9 = 9216
//   Pwh    : uint2   * 128*9 = 9216  (4 x fp16 corner weights)
#define A_OFF    0
#define A_BUF_B  18432
#define W_OFF    36864
#define W_TAP_B  9216
#define PI_OFF   55296
#define PWH_OFF  64512
#define SMEM_BYTES 73728

__device__ __half g_xh[(size_t)B_N * HW * C_IN];   // NHWC fp16 x, 8 MB
__device__ __half g_w[NTAP * C_IN * WLD];          // [k][cin][cout+pad] fp16

__device__ __forceinline__ uint32_t smem_u32(const void* p) {
    uint32_t a;
    asm("{ .reg .u64 t; cvta.to.shared.u64 t, %1; cvt.u32.u64 %0, t; }" : "=r"(a) : "l"(p));
    return a;
}
__device__ __forceinline__ void cp_async16(uint32_t dst, const void* src) {
    asm volatile("cp.async.cg.shared.global [%0], [%1], 16;" :: "r"(dst), "l"(src));
}
#define CP_COMMIT() asm volatile("cp.async.commit_group;" ::: "memory")
#define CP_WAIT0()  asm volatile("cp.async.wait_group 0;" ::: "memory")

// ---- fused prepass: NCHW fp32 -> NHWC fp16 transpose  +  weight prep ----
#define T_BLOCKS (B_N * HW / 64)     // 1024
__global__ __launch_bounds__(256)
void prepass(const float* __restrict__ x, const float* __restrict__ w) {
    const int blk = blockIdx.x;
    const int t   = threadIdx.x;

    if (blk >= T_BLOCKS) {           // ---- weight prep: one tap per block ----
        const int k = blk - T_BLOCKS;
#pragma unroll
        for (int i = t; i < C_IN * C_OUT; i += 256) {
            const int cin  = i >> 6;
            const int cout = i & 63;
            g_w[(k * C_IN + cin) * WLD + cout] =
                __float2half_rn(w[(cout * C_IN + cin) * NTAP + k]);
        }
        return;
    }

    // ---- transpose tile: batch b, hw0..hw0+63, all 64 channels ----
    __shared__ float tile[64][65];
    const int b   = blk >> 9;
    const int hw0 = (blk & 511) * 64;
    const float* xb = x + (size_t)b * C_IN * HW;
    __half* xtb = g_xh + (size_t)b * HW * C_IN;

    {
        const int f4 = t & 15;
        const int c0 = t >> 4;
#pragma unroll
        for (int pass = 0; pass < 4; pass++) {
            const int c = c0 + pass * 16;
            const float4 v = __ldg((const float4*)(xb + (size_t)c * HW + hw0) + f4);
            tile[c][f4 * 4 + 0] = v.x;
            tile[c][f4 * 4 + 1] = v.y;
            tile[c][f4 * 4 + 2] = v.z;
            tile[c][f4 * 4 + 3] = v.w;
        }
    }
    __syncthreads();

#pragma unroll
    for (int u = t; u < 64 * 8; u += 256) {
        const int hw = u >> 3;
        const int cg = u & 7;
        uint4 q;
        __half2* h = (__half2*)&q;
#pragma unroll
        for (int j = 0; j < 4; j++)
            h[j] = __floats2half2_rn(tile[cg * 8 + 2 * j][hw],
                                     tile[cg * 8 + 2 * j + 1][hw]);
        *(uint4*)(xtb + (size_t)(hw0 + hw) * C_IN + cg * 8) = q;
    }
}

// ---- main ----
__global__ __launch_bounds__(TPB, 3)
void deform_mma(const float* __restrict__ offset,
                const float* __restrict__ bias,
                float* __restrict__ out) {
    extern __shared__ char sm[];
    ushort4* Pidx = (ushort4*)(sm + PI_OFF);   // [tap*128+px] corner indices
    uint2*   Pwh  = (uint2*)(sm + PWH_OFF);    // [tap*128+px] 4 x fp16 weights
    float*   Bsm  = (float*)(sm + A_OFF);      // bias tile, overlaid in A buf 0

    const int tid = threadIdx.x;
    const int wid = tid >> 5;

    const int p0  = blockIdx.x * TPX;
    const int b   = p0 >> 15;
    const int rem = p0 & (HWO - 1);
    const int ho  = rem >> 8;
    const int wo0 = rem & (W_O - 1);

    const float* offb = offset + (size_t)b * 2 * NTAP * HWO + rem;
    const __half* xhb = g_xh + (size_t)b * HW * C_IN;
    const uint32_t wsm = smem_u32(sm + W_OFF);

    // prefetch tap-0 weights
    {
        const char* src = (const char*)(g_w);
        for (int i = tid; i < W_TAP_B / 16; i += TPB)
            cp_async16(wsm + i * 16, src + i * 16);
        CP_COMMIT();
    }
    // bias broadcast tile (in A buf 0, consumed before first fill)
    for (int i = tid; i < 16 * 64; i += TPB) {
        int r = i >> 6, c = i & 63;
        Bsm[r * 68 + c] = __ldg(bias + c);
    }

    // precompute bilinear params for ALL taps: 9*128 units
    for (int u = tid; u < NTAP * TPX; u += TPB) {
        const int k  = u >> 7;
        const int p  = u & 127;
        const float offy = __ldg(offb + (2 * k + 0) * HWO + p);
        const float offx = __ldg(offb + (2 * k + 1) * HWO + p);
        const float py = (float)(ho - 1 + k / 3) + offy;
        const float px = (float)(wo0 + p - 1 + k % 3) + offx;
        const float y0f = floorf(py);
        const float x0f = floorf(px);
        const int   y0  = (int)y0f;
        const int   x0  = (int)x0f;
        const float wy  = py - y0f;
        const float wx  = px - x0f;
        const int   y1  = y0 + 1;
        const int   x1  = x0 + 1;
        const bool vy0 = (y0 >= 0) && (y0 < H_IN);
        const bool vy1 = (y1 >= 0) && (y1 < H_IN);
        const bool vx0 = (x0 >= 0) && (x0 < W_IN);
        const bool vx1 = (x1 >= 0) && (x1 < W_IN);
        const int cy0 = min(max(y0, 0), H_IN - 1);
        const int cy1 = min(max(y1, 0), H_IN - 1);
        const int cx0 = min(max(x0, 0), W_IN - 1);
        const int cx1 = min(max(x1, 0), W_IN - 1);
        ushort4 pi;
        pi.x = (unsigned short)(cy0 * W_IN + cx0);
        pi.y = (unsigned short)(cy0 * W_IN + cx1);
        pi.z = (unsigned short)(cy1 * W_IN + cx0);
        pi.w = (unsigned short)(cy1 * W_IN + cx1);
        const float w00 = (vy0 && vx0) ? (1.0f - wy) * (1.0f - wx) : 0.0f;
        const float w01 = (vy0 && vx1) ? (1.0f - wy) * wx          : 0.0f;
        const float w10 = (vy1 && vx0) ? wy * (1.0f - wx)          : 0.0f;
        const float w11 = (vy1 && vx1) ? wy * wx                   : 0.0f;
        uint2 pw;
        const __half2 h01 = __floats2half2_rn(w00, w01);
        const __half2 h23 = __floats2half2_rn(w10, w11);
        pw.x = *(const uint32_t*)&h01;
        pw.y = *(const uint32_t*)&h23;
        Pidx[u] = pi;
        Pwh[u]  = pw;
    }
    __syncthreads();

    // accumulators preloaded with bias
    wmma::fragment<wmma::accumulator, 16, 16, 16, float> acc[4];
#pragma unroll
    for (int n = 0; n < 4; n++)
        wmma::load_matrix_sync(acc[n], Bsm + n * 16, 68, wmma::mem_row_major);
    __syncthreads();   // all warps done reading Bsm before fill overwrites it

    // fill one tap into a given A buffer.
    // mapping: thread owns ONE pixel (px = tid>>1) and 4 channel-groups
    // (cg = (tid&1)*4 + i) -> params loaded once; STS pattern conflict-free.
    auto fill_tap = [&](int k, int buf) {
        __half* A = (__half*)(sm + A_OFF + buf * A_BUF_B);
        const int px  = tid >> 1;
        const int cg0 = (tid & 1) * 4;
        const ushort4 pi = Pidx[k * TPX + px];
        const uint2   pw = Pwh[k * TPX + px];
        const __half2 hw01 = *(const __half2*)&pw.x;
        const __half2 hw23 = *(const __half2*)&pw.y;
        const __half2 w00 = __half2half2(__low2half(hw01));
        const __half2 w01 = __half2half2(__high2half(hw01));
        const __half2 w10 = __half2half2(__low2half(hw23));
        const __half2 w11 = __half2half2(__high2half(hw23));
        const uint4* r00 = (const uint4*)(xhb + (size_t)pi.x * C_IN);
        const uint4* r01 = (const uint4*)(xhb + (size_t)pi.y * C_IN);
        const uint4* r10 = (const uint4*)(xhb + (size_t)pi.z * C_IN);
        const uint4* r11 = (const uint4*)(xhb + (size_t)pi.w * C_IN);
#pragma unroll
        for (int i = 0; i < 4; i++) {
            const int cg = cg0 + i;
            const uint4 v00 = __ldg(r00 + cg);
            const uint4 v01 = __ldg(r01 + cg);
            const uint4 v10 = __ldg(r10 + cg);
            const uint4 v11 = __ldg(r11 + cg);
            const __half2* c00 = (const __half2*)&v00;
            const __half2* c01 = (const __half2*)&v01;
            const __half2* c10 = (const __half2*)&v10;
            const __half2* c11 = (const __half2*)&v11;
            uint4 hq;
            __half2* hh = (__half2*)&hq;
#pragma unroll
            for (int j = 0; j < 4; j++) {
                __half2 r = __hmul2(c11[j], w11);
                r = __hfma2(c10[j], w10, r);
                r = __hfma2(c01[j], w01, r);
                r = __hfma2(c00[j], w00, r);
                hh[j] = r;
            }
            *(uint4*)(A + px * ALD + cg * 8) = hq;
        }
    };

    // prologue: fill tap 0, ensure W0 resident
    fill_tap(0, 0);
    CP_WAIT0();
    __syncthreads();

    for (int k = 0; k < NTAP; k++) {
        // issue next tap's weight prefetch + fill next tap's A (overlaps GEMM)
        const int kn = k + 1;
        if (kn < NTAP) {
            const char* src = (const char*)(g_w + (size_t)kn * C_IN * WLD);
            const uint32_t dst = wsm + (kn & 1) * W_TAP_B;
            for (int i = tid; i < W_TAP_B / 16; i += TPB)
                cp_async16(dst + i * 16, src + i * 16);
            CP_COMMIT();
            fill_tap(kn, kn & 1);
        }

        // GEMM: acc += Ah*Wh   (warp = 16 px rows)
        const __half* Wh = (const __half*)(sm + W_OFF + (k & 1) * W_TAP_B);
        const __half* Ahw = (const __half*)(sm + A_OFF + (k & 1) * A_BUF_B) + wid * 16 * ALD;
#pragma unroll
        for (int kc = 0; kc < 4; kc++) {
            wmma::fragment<wmma::matrix_a, 16, 16, 16, __half, wmma::row_major> a_h;
            wmma::load_matrix_sync(a_h, Ahw + kc * 16, ALD);
#pragma unroll
            for (int n = 0; n < 4; n++) {
                wmma::fragment<wmma::matrix_b, 16, 16, 16, __half, wmma::row_major> b_h;
                wmma::load_matrix_sync(b_h, Wh + kc * 16 * WLD + n * 16, WLD);
                wmma::mma_sync(acc[n], a_h, b_h, acc[n]);
            }
        }

        CP_WAIT0();        // next tap's W resident (all threads, before barrier)
        __syncthreads();   // A/W buffers safe to reuse; fills visible
    }

    // epilogue: direct col-major store -> out[b][cout][px], bias already in acc
    float* ob = out + (size_t)b * C_OUT * HWO + rem + wid * 16;
#pragma unroll
    for (int n = 0; n < 4; n++)
        wmma::store_matrix_sync(ob + (size_t)(n * 16) * HWO, acc[n], HWO,
                                wmma::mem_col_major);
}

extern "C" void kernel_launch(void* const* d_in, const int* in_sizes, int n_in,
                              void* d_out, int out_size) {
    const float* x      = (const float*)d_in[0];
    const float* offset = (const float*)d_in[1];
    const float* weight = (const float*)d_in[2];
    const float* bias   = (const float*)d_in[3];
    float* out = (float*)d_out;
    (void)in_sizes; (void)n_in; (void)out_size;

    cudaFuncSetAttribute(deform_mma,
                         cudaFuncAttributeMaxDynamicSharedMemorySize, SMEM_BYTES);

    prepass<<<T_BLOCKS + NTAP, 256>>>(x, weight);
    deform_mma<<<NPIX / TPX, TPB, SMEM_BYTES>>>(offset, bias, out);
}

// round 12
// speedup vs baseline: 1.5361x; 1.5361x over previous
#include <cuda_runtime.h>
#include <cuda_fp16.h>
#include <mma.h>
#include <cstdint>

using namespace nvcuda;

// Deformable conv2d: B=2, CIN=64, H=128, W=256, COUT=64, K=3, s=1, p=1, d=1
#define B_N   2
#define C_IN  64
#define H_IN  128
#define W_IN  256
#define C_OUT 64
#define NTAP  9
#define H_O   128
#define W_O   256
#define HW    (H_IN * W_IN)     // 32768
#define HWO   (H_O * W_O)       // 32768
#define NPIX  (B_N * HWO)       // 65536

#define TPX   128               // pixels (M) per CTA tile
#define TPB   256               // 8 warps

#define ALD   72                // A smem leading dim (fp16), mult of 8
#define WLD   72                // W smem leading dim

// dynamic smem (bytes), 72 KB total -> 3 CTAs/SM:
//   A bufs : 2 * 128*72*2 = 36864   (bias tile overlaid at start of buf 0)
//   W bufs : 2 * 64*72*2  = 18432
//   Pidx   : ushort4 * 128*9 = 9216
//   Pwh    : uint2   * 128*9 = 9216  (4 x fp16 corner weights)
#define A_OFF    0
#define A_BUF_B  18432
#define W_OFF    36864
#define W_TAP_B  9216
#define PI_OFF   55296
#define PWH_OFF  64512
#define SMEM_BYTES 73728

__device__ __half g_xh[(size_t)B_N * HW * C_IN];   // NHWC fp16 x, 8 MB
__device__ __half g_w[NTAP * C_IN * WLD];          // [k][cin][cout+pad] fp16

__device__ __forceinline__ uint32_t smem_u32(const void* p) {
    uint32_t a;
    asm("{ .reg .u64 t; cvta.to.shared.u64 t, %1; cvt.u32.u64 %0, t; }" : "=r"(a) : "l"(p));
    return a;
}
__device__ __forceinline__ void cp_async16(uint32_t dst, const void* src) {
    asm volatile("cp.async.cg.shared.global [%0], [%1], 16;" :: "r"(dst), "l"(src));
}
#define CP_COMMIT() asm volatile("cp.async.commit_group;" ::: "memory")
#define CP_WAIT0()  asm volatile("cp.async.wait_group 0;" ::: "memory")

// ---- fused prepass: NCHW fp32 -> NHWC fp16 transpose  +  weight prep ----
#define T_BLOCKS (B_N * HW / 64)     // 1024
__global__ __launch_bounds__(256)
void prepass(const float* __restrict__ x, const float* __restrict__ w) {
    const int blk = blockIdx.x;
    const int t   = threadIdx.x;

    if (blk >= T_BLOCKS) {           // ---- weight prep: one tap per block ----
        const int k = blk - T_BLOCKS;
#pragma unroll
        for (int i = t; i < C_IN * C_OUT; i += 256) {
            const int cin  = i >> 6;
            const int cout = i & 63;
            g_w[(k * C_IN + cin) * WLD + cout] =
                __float2half_rn(w[(cout * C_IN + cin) * NTAP + k]);
        }
        return;
    }

    // ---- transpose tile: batch b, hw0..hw0+63, all 64 channels ----
    __shared__ float tile[64][65];
    const int b   = blk >> 9;
    const int hw0 = (blk & 511) * 64;
    const float* xb = x + (size_t)b * C_IN * HW;
    __half* xtb = g_xh + (size_t)b * HW * C_IN;

    {
        const int f4 = t & 15;
        const int c0 = t >> 4;
#pragma unroll
        for (int pass = 0; pass < 4; pass++) {
            const int c = c0 + pass * 16;
            const float4 v = __ldg((const float4*)(xb + (size_t)c * HW + hw0) + f4);
            tile[c][f4 * 4 + 0] = v.x;
            tile[c][f4 * 4 + 1] = v.y;
            tile[c][f4 * 4 + 2] = v.z;
            tile[c][f4 * 4 + 3] = v.w;
        }
    }
    __syncthreads();

#pragma unroll
    for (int u = t; u < 64 * 8; u += 256) {
        const int hw = u >> 3;
        const int cg = u & 7;
        uint4 q;
        __half2* h = (__half2*)&q;
#pragma unroll
        for (int j = 0; j < 4; j++)
            h[j] = __floats2half2_rn(tile[cg * 8 + 2 * j][hw],
                                     tile[cg * 8 + 2 * j + 1][hw]);
        *(uint4*)(xtb + (size_t)(hw0 + hw) * C_IN + cg * 8) = q;
    }
}

// ---- main ----
__global__ __launch_bounds__(TPB, 3)
void deform_mma(const float* __restrict__ offset,
                const float* __restrict__ bias,
                float* __restrict__ out) {
    extern __shared__ char sm[];
    ushort4* Pidx = (ushort4*)(sm + PI_OFF);   // [tap*128+px] corner indices
    uint2*   Pwh  = (uint2*)(sm + PWH_OFF);    // [tap*128+px] 4 x fp16 weights
    float*   Bsm  = (float*)(sm + A_OFF);      // bias tile, overlaid in A buf 0

    const int tid = threadIdx.x;
    const int wid = tid >> 5;

    const int p0  = blockIdx.x * TPX;
    const int b   = p0 >> 15;
    const int rem = p0 & (HWO - 1);
    const int ho  = rem >> 8;
    const int wo0 = rem & (W_O - 1);

    const float* offb = offset + (size_t)b * 2 * NTAP * HWO + rem;
    const __half* xhb = g_xh + (size_t)b * HW * C_IN;
    const uint32_t wsm = smem_u32(sm + W_OFF);

    // prefetch tap-0 weights
    {
        const char* src = (const char*)(g_w);
        for (int i = tid; i < W_TAP_B / 16; i += TPB)
            cp_async16(wsm + i * 16, src + i * 16);
        CP_COMMIT();
    }
    // bias broadcast tile (in A buf 0, consumed before first fill)
    for (int i = tid; i < 16 * 64; i += TPB) {
        int r = i >> 6, c = i & 63;
        Bsm[r * 68 + c] = __ldg(bias + c);
    }

    // precompute bilinear params for ALL taps: 9*128 units
    for (int u = tid; u < NTAP * TPX; u += TPB) {
        const int k  = u >> 7;
        const int p  = u & 127;
        const float offy = __ldg(offb + (2 * k + 0) * HWO + p);
        const float offx = __ldg(offb + (2 * k + 1) * HWO + p);
        const float py = (float)(ho - 1 + k / 3) + offy;
        const float px = (float)(wo0 + p - 1 + k % 3) + offx;
        const float y0f = floorf(py);
        const float x0f = floorf(px);
        const int   y0  = (int)y0f;
        const int   x0  = (int)x0f;
        const float wy  = py - y0f;
        const float wx  = px - x0f;
        const int   y1  = y0 + 1;
        const int   x1  = x0 + 1;
        const bool vy0 = (y0 >= 0) && (y0 < H_IN);
        const bool vy1 = (y1 >= 0) && (y1 < H_IN);
        const bool vx0 = (x0 >= 0) && (x0 < W_IN);
        const bool vx1 = (x1 >= 0) && (x1 < W_IN);
        const int cy0 = min(max(y0, 0), H_IN - 1);
        const int cy1 = min(max(y1, 0), H_IN - 1);
        const int cx0 = min(max(x0, 0), W_IN - 1);
        const int cx1 = min(max(x1, 0), W_IN - 1);
        ushort4 pi;
        pi.x = (unsigned short)(cy0 * W_IN + cx0);
        pi.y = (unsigned short)(cy0 * W_IN + cx1);
        pi.z = (unsigned short)(cy1 * W_IN + cx0);
        pi.w = (unsigned short)(cy1 * W_IN + cx1);
        const float w00 = (vy0 && vx0) ? (1.0f - wy) * (1.0f - wx) : 0.0f;
        const float w01 = (vy0 && vx1) ? (1.0f - wy) * wx          : 0.0f;
        const float w10 = (vy1 && vx0) ? wy * (1.0f - wx)          : 0.0f;
        const float w11 = (vy1 && vx1) ? wy * wx                   : 0.0f;
        uint2 pw;
        const __half2 h01 = __floats2half2_rn(w00, w01);
        const __half2 h23 = __floats2half2_rn(w10, w11);
        pw.x = *(const uint32_t*)&h01;
        pw.y = *(const uint32_t*)&h23;
        Pidx[u] = pi;
        Pwh[u]  = pw;
    }
    __syncthreads();

    // accumulators preloaded with bias
    wmma::fragment<wmma::accumulator, 16, 16, 16, float> acc[4];
#pragma unroll
    for (int n = 0; n < 4; n++)
        wmma::load_matrix_sync(acc[n], Bsm + n * 16, 68, wmma::mem_row_major);
    __syncthreads();   // all warps done reading Bsm before fill overwrites it

    // fill one tap into a given A buffer: 1024 units (px, 8-ch group).
    // COALESCED mapping: 8 consecutive lanes = 8 channel groups of ONE pixel
    // corner row -> 128B coalesced LDG per corner. Params LDS = broadcast.
    // Interp in packed half2 (HFMA2), no f32 converts.
    auto fill_tap = [&](int k, int buf) {
        __half* A = (__half*)(sm + A_OFF + buf * A_BUF_B);
#pragma unroll
        for (int i = 0; i < 4; i++) {
            const int u  = tid + TPB * i;
            const int cg = u & 7;        // channel group of 8
            const int px = u >> 3;       // pixel in tile
            const ushort4 pi = Pidx[k * TPX + px];
            const uint2   pw = Pwh[k * TPX + px];
            const __half2 hw01 = *(const __half2*)&pw.x;
            const __half2 hw23 = *(const __half2*)&pw.y;
            const __half2 w00 = __half2half2(__low2half(hw01));
            const __half2 w01 = __half2half2(__high2half(hw01));
            const __half2 w10 = __half2half2(__low2half(hw23));
            const __half2 w11 = __half2half2(__high2half(hw23));
            const uint4 v00 = __ldg((const uint4*)(xhb + (size_t)pi.x * C_IN) + cg);
            const uint4 v01 = __ldg((const uint4*)(xhb + (size_t)pi.y * C_IN) + cg);
            const uint4 v10 = __ldg((const uint4*)(xhb + (size_t)pi.z * C_IN) + cg);
            const uint4 v11 = __ldg((const uint4*)(xhb + (size_t)pi.w * C_IN) + cg);
            const __half2* c00 = (const __half2*)&v00;
            const __half2* c01 = (const __half2*)&v01;
            const __half2* c10 = (const __half2*)&v10;
            const __half2* c11 = (const __half2*)&v11;
            uint4 hq;
            __half2* hh = (__half2*)&hq;
#pragma unroll
            for (int j = 0; j < 4; j++) {
                __half2 r = __hmul2(c11[j], w11);
                r = __hfma2(c10[j], w10, r);
                r = __hfma2(c01[j], w01, r);
                r = __hfma2(c00[j], w00, r);
                hh[j] = r;
            }
            *(uint4*)(A + px * ALD + cg * 8) = hq;
        }
    };

    // prologue: fill tap 0, ensure W0 resident
    fill_tap(0, 0);
    CP_WAIT0();
    __syncthreads();

    for (int k = 0; k < NTAP; k++) {
        // issue next tap's weight prefetch + fill next tap's A (overlaps GEMM)
        const int kn = k + 1;
        if (kn < NTAP) {
            const char* src = (const char*)(g_w + (size_t)kn * C_IN * WLD);
            const uint32_t dst = wsm + (kn & 1) * W_TAP_B;
            for (int i = tid; i < W_TAP_B / 16; i += TPB)
                cp_async16(dst + i * 16, src + i * 16);
            CP_COMMIT();
            fill_tap(kn, kn & 1);
        }

        // GEMM: acc += Ah*Wh   (warp = 16 px rows)
        const __half* Wh = (const __half*)(sm + W_OFF + (k & 1) * W_TAP_B);
        const __half* Ahw = (const __half*)(sm + A_OFF + (k & 1) * A_BUF_B) + wid * 16 * ALD;
#pragma unroll
        for (int kc = 0; kc < 4; kc++) {
            wmma::fragment<wmma::matrix_a, 16, 16, 16, __half, wmma::row_major> a_h;
            wmma::load_matrix_sync(a_h, Ahw + kc * 16, ALD);
#pragma unroll
            for (int n = 0; n < 4; n++) {
                wmma::fragment<wmma::matrix_b, 16, 16, 16, __half, wmma::row_major> b_h;
                wmma::load_matrix_sync(b_h, Wh + kc * 16 * WLD + n * 16, WLD);
                wmma::mma_sync(acc[n], a_h, b_h, acc[n]);
            }
        }

        CP_WAIT0();        // next tap's W resident (all threads, before barrier)
        __syncthreads();   // A/W buffers safe to reuse; fills visible
    }

    // epilogue: direct col-major store -> out[b][cout][px], bias already in acc
    float* ob = out + (size_t)b * C_OUT * HWO + rem + wid * 16;
#pragma unroll
    for (int n = 0; n < 4; n++)
        wmma::store_matrix_sync(ob + (size_t)(n * 16) * HWO, acc[n], HWO,
                                wmma::mem_col_major);
}

extern "C" void kernel_launch(void* const* d_in, const int* in_sizes, int n_in,
                              void* d_out, int out_size) {
    const float* x      = (const float*)d_in[0];
    const float* offset = (const float*)d_in[1];
    const float* weight = (const float*)d_in[2];
    const float* bias   = (const float*)d_in[3];
    float* out = (float*)d_out;
    (void)in_sizes; (void)n_in; (void)out_size;

    cudaFuncSetAttribute(deform_mma,
                         cudaFuncAttributeMaxDynamicSharedMemorySize, SMEM_BYTES);

    prepass<<<T_BLOCKS + NTAP, 256>>>(x, weight);
    deform_mma<<<NPIX / TPX, TPB, SMEM_BYTES>>>(offset, bias, out);
}

// round 13
// speedup vs baseline: 1.7262x; 1.1237x over previous
#include <cuda_runtime.h>
#include <cuda_fp16.h>
#include <mma.h>
#include <cstdint>

using namespace nvcuda;

// Deformable conv2d: B=2, CIN=64, H=128, W=256, COUT=64, K=3, s=1, p=1, d=1
#define B_N   2
#define C_IN  64
#define H_IN  128
#define W_IN  256
#define C_OUT 64
#define NTAP  9
#define H_O   128
#define W_O   256
#define HW    (H_IN * W_IN)     // 32768
#define HWO   (H_O * W_O)       // 32768
#define NPIX  (B_N * HWO)       // 65536

#define TPX   128               // pixels (M) per CTA tile
#define TPB   256               // 8 warps

#define ALD   72                // A smem leading dim (fp16), mult of 8
#define WLD   72                // W smem leading dim

// dynamic smem (bytes), 72 KB total -> 3 CTAs/SM:
#define A_OFF    0
#define A_BUF_B  18432
#define W_OFF    36864
#define W_TAP_B  9216
#define PI_OFF   55296
#define PWH_OFF  64512
#define SMEM_BYTES 73728

__device__ __half g_xh[(size_t)B_N * HW * C_IN];   // NHWC fp16 x, 8 MB
__device__ __half g_w[NTAP * C_IN * WLD];          // [k][cin][cout+pad] fp16

__device__ __forceinline__ uint32_t smem_u32(const void* p) {
    uint32_t a;
    asm("{ .reg .u64 t; cvta.to.shared.u64 t, %1; cvt.u32.u64 %0, t; }" : "=r"(a) : "l"(p));
    return a;
}
__device__ __forceinline__ void cp_async16(uint32_t dst, const void* src) {
    asm volatile("cp.async.cg.shared.global [%0], [%1], 16;" :: "r"(dst), "l"(src));
}
#define CP_COMMIT() asm volatile("cp.async.commit_group;" ::: "memory")
#define CP_WAIT0()  asm volatile("cp.async.wait_group 0;" ::: "memory")

// ---- fused prepass: NCHW fp32 -> NHWC fp16 transpose  +  weight prep ----
#define T_BLOCKS (B_N * HW / 64)     // 1024
__global__ __launch_bounds__(256)
void prepass(const float* __restrict__ x, const float* __restrict__ w) {
    const int blk = blockIdx.x;
    const int t   = threadIdx.x;

    if (blk >= T_BLOCKS) {           // ---- weight prep: one tap per block ----
        const int k = blk - T_BLOCKS;
#pragma unroll
        for (int i = t; i < C_IN * C_OUT; i += 256) {
            const int cin  = i >> 6;
            const int cout = i & 63;
            g_w[(k * C_IN + cin) * WLD + cout] =
                __float2half_rn(w[(cout * C_IN + cin) * NTAP + k]);
        }
        return;
    }

    // ---- transpose tile: batch b, hw0..hw0+63, all 64 channels ----
    __shared__ float tile[64][65];
    const int b   = blk >> 9;
    const int hw0 = (blk & 511) * 64;
    const float* xb = x + (size_t)b * C_IN * HW;
    __half* xtb = g_xh + (size_t)b * HW * C_IN;

    {
        const int f4 = t & 15;
        const int c0 = t >> 4;
#pragma unroll
        for (int pass = 0; pass < 4; pass++) {
            const int c = c0 + pass * 16;
            const float4 v = __ldg((const float4*)(xb + (size_t)c * HW + hw0) + f4);
            tile[c][f4 * 4 + 0] = v.x;
            tile[c][f4 * 4 + 1] = v.y;
            tile[c][f4 * 4 + 2] = v.z;
            tile[c][f4 * 4 + 3] = v.w;
        }
    }
    __syncthreads();

#pragma unroll
    for (int u = t; u < 64 * 8; u += 256) {
        const int hw = u >> 3;
        const int cg = u & 7;
        uint4 q;
        __half2* h = (__half2*)&q;
#pragma unroll
        for (int j = 0; j < 4; j++)
            h[j] = __floats2half2_rn(tile[cg * 8 + 2 * j][hw],
                                     tile[cg * 8 + 2 * j + 1][hw]);
        *(uint4*)(xtb + (size_t)(hw0 + hw) * C_IN + cg * 8) = q;
    }
}

// ---- main ----
__global__ __launch_bounds__(TPB, 3)
void deform_mma(const float* __restrict__ offset,
                const float* __restrict__ bias,
                float* __restrict__ out) {
    extern __shared__ char sm[];
    ushort4* Pidx = (ushort4*)(sm + PI_OFF);   // [tap*128+px] corner indices
    uint2*   Pwh  = (uint2*)(sm + PWH_OFF);    // [tap*128+px] 4 x fp16 weights
    float*   Bsm  = (float*)(sm + A_OFF);      // bias tile, overlaid in A buf 0

    const int tid = threadIdx.x;
    const int wid = tid >> 5;
    const int wm  = (wid >> 1) * 32;    // warp M origin (px)
    const int wn  = (wid & 1) * 32;     // warp N origin (cout)

    const int p0  = blockIdx.x * TPX;
    const int b   = p0 >> 15;
    const int rem = p0 & (HWO - 1);
    const int ho  = rem >> 8;
    const int wo0 = rem & (W_O - 1);

    const float* offb = offset + (size_t)b * 2 * NTAP * HWO + rem;
    const __half* xhb = g_xh + (size_t)b * HW * C_IN;
    const uint32_t wsm = smem_u32(sm + W_OFF);

    // prefetch tap-0 weights
    {
        const char* src = (const char*)(g_w);
        for (int i = tid; i < W_TAP_B / 16; i += TPB)
            cp_async16(wsm + i * 16, src + i * 16);
        CP_COMMIT();
    }
    // bias broadcast tile (in A buf 0, consumed before first fill)
    for (int i = tid; i < 16 * 64; i += TPB) {
        int r = i >> 6, c = i & 63;
        Bsm[r * 68 + c] = __ldg(bias + c);
    }

    // precompute bilinear params for ALL taps: 9*128 units
    for (int u = tid; u < NTAP * TPX; u += TPB) {
        const int k  = u >> 7;
        const int p  = u & 127;
        const float offy = __ldg(offb + (2 * k + 0) * HWO + p);
        const float offx = __ldg(offb + (2 * k + 1) * HWO + p);
        const float py = (float)(ho - 1 + k / 3) + offy;
        const float px = (float)(wo0 + p - 1 + k % 3) + offx;
        const float y0f = floorf(py);
        const float x0f = floorf(px);
        const int   y0  = (int)y0f;
        const int   x0  = (int)x0f;
        const float wy  = py - y0f;
        const float wx  = px - x0f;
        const int   y1  = y0 + 1;
        const int   x1  = x0 + 1;
        const bool vy0 = (y0 >= 0) && (y0 < H_IN);
        const bool vy1 = (y1 >= 0) && (y1 < H_IN);
        const bool vx0 = (x0 >= 0) && (x0 < W_IN);
        const bool vx1 = (x1 >= 0) && (x1 < W_IN);
        const int cy0 = min(max(y0, 0), H_IN - 1);
        const int cy1 = min(max(y1, 0), H_IN - 1);
        const int cx0 = min(max(x0, 0), W_IN - 1);
        const int cx1 = min(max(x1, 0), W_IN - 1);
        ushort4 pi;
        pi.x = (unsigned short)(cy0 * W_IN + cx0);
        pi.y = (unsigned short)(cy0 * W_IN + cx1);
        pi.z = (unsigned short)(cy1 * W_IN + cx0);
        pi.w = (unsigned short)(cy1 * W_IN + cx1);
        const float w00 = (vy0 && vx0) ? (1.0f - wy) * (1.0f - wx) : 0.0f;
        const float w01 = (vy0 && vx1) ? (1.0f - wy) * wx          : 0.0f;
        const float w10 = (vy1 && vx0) ? wy * (1.0f - wx)          : 0.0f;
        const float w11 = (vy1 && vx1) ? wy * wx                   : 0.0f;
        uint2 pw;
        const __half2 h01 = __floats2half2_rn(w00, w01);
        const __half2 h23 = __floats2half2_rn(w10, w11);
        pw.x = *(const uint32_t*)&h01;
        pw.y = *(const uint32_t*)&h23;
        Pidx[u] = pi;
        Pwh[u]  = pw;
    }
    __syncthreads();

    // accumulators preloaded with bias; warp tile = 32px x 32cout
    wmma::fragment<wmma::accumulator, 16, 16, 16, float> acc[2][2];
#pragma unroll
    for (int i = 0; i < 2; i++)
#pragma unroll
        for (int j = 0; j < 2; j++)
            wmma::load_matrix_sync(acc[i][j], Bsm + wn + j * 16, 68,
                                   wmma::mem_row_major);
    __syncthreads();   // all warps done reading Bsm before fill overwrites it

    // fill one tap into a given A buffer. Coalesced: 8 consecutive lanes =
    // 8 channel groups of one pixel corner row. cg constant per thread;
    // px = tid>>3 + 32*i. Manually software-pipelined (next unit's loads
    // issued before current unit's interp) to double gather MLP.
    auto fill_tap = [&](int k, int buf) {
        __half* A = (__half*)(sm + A_OFF + buf * A_BUF_B);
        const int cg  = tid & 7;
        const int px0 = tid >> 3;
        const int base = k * TPX;

        ushort4 pi = Pidx[base + px0];
        uint2   pw = Pwh[base + px0];
        uint4 c00 = __ldg((const uint4*)(xhb + (size_t)pi.x * C_IN) + cg);
        uint4 c01 = __ldg((const uint4*)(xhb + (size_t)pi.y * C_IN) + cg);
        uint4 c10 = __ldg((const uint4*)(xhb + (size_t)pi.z * C_IN) + cg);
        uint4 c11 = __ldg((const uint4*)(xhb + (size_t)pi.w * C_IN) + cg);

#pragma unroll
        for (int i = 0; i < 4; i++) {
            uint4 n00, n01, n10, n11;
            uint2 npw;
            if (i < 3) {             // stage next unit's loads (overlaps interp)
                const ushort4 npi = Pidx[base + px0 + 32 * (i + 1)];
                npw = Pwh[base + px0 + 32 * (i + 1)];
                n00 = __ldg((const uint4*)(xhb + (size_t)npi.x * C_IN) + cg);
                n01 = __ldg((const uint4*)(xhb + (size_t)npi.y * C_IN) + cg);
                n10 = __ldg((const uint4*)(xhb + (size_t)npi.z * C_IN) + cg);
                n11 = __ldg((const uint4*)(xhb + (size_t)npi.w * C_IN) + cg);
            }
            {
                const __half2 hw01 = *(const __half2*)&pw.x;
                const __half2 hw23 = *(const __half2*)&pw.y;
                const __half2 w00 = __half2half2(__low2half(hw01));
                const __half2 w01 = __half2half2(__high2half(hw01));
                const __half2 w10 = __half2half2(__low2half(hw23));
                const __half2 w11 = __half2half2(__high2half(hw23));
                const __half2* h00 = (const __half2*)&c00;
                const __half2* h01p = (const __half2*)&c01;
                const __half2* h10 = (const __half2*)&c10;
                const __half2* h11 = (const __half2*)&c11;
                uint4 hq;
                __half2* hh = (__half2*)&hq;
#pragma unroll
                for (int j = 0; j < 4; j++) {
                    __half2 r = __hmul2(h11[j], w11);
                    r = __hfma2(h10[j], w10, r);
                    r = __hfma2(h01p[j], w01, r);
                    r = __hfma2(h00[j], w00, r);
                    hh[j] = r;
                }
                *(uint4*)(A + (px0 + 32 * i) * ALD + cg * 8) = hq;
            }
            if (i < 3) {
                c00 = n00; c01 = n01; c10 = n10; c11 = n11; pw = npw;
            }
        }
    };

    // prologue: fill tap 0, ensure W0 resident
    fill_tap(0, 0);
    CP_WAIT0();
    __syncthreads();

    for (int k = 0; k < NTAP; k++) {
        // issue next tap's weight prefetch + fill next tap's A (overlaps GEMM)
        const int kn = k + 1;
        if (kn < NTAP) {
            const char* src = (const char*)(g_w + (size_t)kn * C_IN * WLD);
            const uint32_t dst = wsm + (kn & 1) * W_TAP_B;
            for (int i = tid; i < W_TAP_B / 16; i += TPB)
                cp_async16(dst + i * 16, src + i * 16);
            CP_COMMIT();
            fill_tap(kn, kn & 1);
        }

        // GEMM: acc[i][j] += A[wm+16i][kc] * W[kc][wn+16j]
        const __half* Wh = (const __half*)(sm + W_OFF + (k & 1) * W_TAP_B);
        const __half* Ab = (const __half*)(sm + A_OFF + (k & 1) * A_BUF_B);
#pragma unroll
        for (int kc = 0; kc < 4; kc++) {
            wmma::fragment<wmma::matrix_a, 16, 16, 16, __half, wmma::row_major> a[2];
            wmma::fragment<wmma::matrix_b, 16, 16, 16, __half, wmma::row_major> bfr[2];
#pragma unroll
            for (int i = 0; i < 2; i++)
                wmma::load_matrix_sync(a[i], Ab + (wm + i * 16) * ALD + kc * 16, ALD);
#pragma unroll
            for (int j = 0; j < 2; j++)
                wmma::load_matrix_sync(bfr[j], Wh + kc * 16 * WLD + wn + j * 16, WLD);
#pragma unroll
            for (int i = 0; i < 2; i++)
#pragma unroll
                for (int j = 0; j < 2; j++)
                    wmma::mma_sync(acc[i][j], a[i], bfr[j], acc[i][j]);
        }

        CP_WAIT0();        // next tap's W resident (all threads, before barrier)
        __syncthreads();   // A/W buffers safe to reuse; fills visible
    }

    // epilogue: direct col-major store -> out[b][cout][px], bias already in acc
    float* ob = out + (size_t)b * C_OUT * HWO + rem;
#pragma unroll
    for (int i = 0; i < 2; i++)
#pragma unroll
        for (int j = 0; j < 2; j++)
            wmma::store_matrix_sync(ob + (size_t)(wn + j * 16) * HWO + wm + i * 16,
                                    acc[i][j], HWO, wmma::mem_col_major);
}

extern "C" void kernel_launch(void* const* d_in, const int* in_sizes, int n_in,
                              void* d_out, int out_size) {
    const float* x      = (const float*)d_in[0];
    const float* offset = (const float*)d_in[1];
    const float* weight = (const float*)d_in[2];
    const float* bias   = (const float*)d_in[3];
    float* out = (float*)d_out;
    (void)in_sizes; (void)n_in; (void)out_size;

    cudaFuncSetAttribute(deform_mma,
                         cudaFuncAttributeMaxDynamicSharedMemorySize, SMEM_BYTES);

    prepass<<<T_BLOCKS + NTAP, 256>>>(x, weight);
    deform_mma<<<NPIX / TPX, TPB, SMEM_BYTES>>>(offset, bias, out);
}